// round 7
// baseline (speedup 1.0000x reference)
#include <cuda_runtime.h>

// Problem constants (fixed shapes)
#define NN      50000
#define CC      32
#define HH      32
#define EE      1600000      // == NN*CC (exploited in prep)
#define NH      1600000
#define NH4     400000
#define FC      64
#define NCLS    2
#define BN_EPS  1e-5f

#define TILES   196          // ceil(NN/256)
#define CNTSZ   (TILES * 256)
#define NPB     96           // nodes per block (multiple of 16)
#define FGRID   521          // ceil(NN/NPB)

// Scratch (device globals; all zero at module load)
__device__ __align__(16) float g_xbn[NN * CC];
__device__ __align__(16) float g_y[NN * HH];
__device__ __align__(16) uint2 g_edges[EE];
__device__ unsigned g_cnt[CNTSZ];       // dst histogram (zeroed by fused tail)
__device__ unsigned g_rowloc[CNTSZ];    // per-tile-local exclusive offsets
__device__ unsigned g_cursor[NN];
__device__ unsigned g_bsum[256];
__device__ unsigned g_tileoff[256];
__device__ float g_hacc[FC];            // zeroed by fused tail
__device__ unsigned g_sem;              // zeroed by fused tail
__device__ unsigned g_scansem;          // zeroed by scan tail

// ---------------------------------------------------------------------------
// Kernel 1: BN + projection y = bn(x) @ (W1+W2) + dst histogram
// ---------------------------------------------------------------------------
__global__ __launch_bounds__(256)
void prep_kernel(const float* __restrict__ x,
                 const float* __restrict__ gamma,
                 const float* __restrict__ beta,
                 const float* __restrict__ mean,
                 const float* __restrict__ var,
                 const float* __restrict__ W,
                 const int*   __restrict__ edge_index) {
    __shared__ float sWs[CC * HH];
    for (int i = threadIdx.x; i < CC * HH; i += 256)
        sWs[i] = W[CC * HH + i] + W[2 * CC * HH + i];
    __syncthreads();

    int i = blockIdx.x * 256 + threadIdx.x;       // exactly 1.6M threads
    int lane = i & 31;

    // histogram (thread i handles edge i; EE == NN*CC)
    atomicAdd(&g_cnt[edge_index[EE + i]], 1u);

    float xv = x[i];
    float s = rsqrtf(var[lane] + BN_EPS) * gamma[lane];
    float xb = (xv - mean[lane]) * s + beta[lane];
    g_xbn[i] = xb;

    float y0 = 0.f, y1 = 0.f, y2 = 0.f, y3 = 0.f;
#pragma unroll
    for (int c = 0; c < CC; c += 4) {
        y0 = fmaf(__shfl_sync(0xffffffffu, xb, c    ), sWs[(c    ) * HH + lane], y0);
        y1 = fmaf(__shfl_sync(0xffffffffu, xb, c + 1), sWs[(c + 1) * HH + lane], y1);
        y2 = fmaf(__shfl_sync(0xffffffffu, xb, c + 2), sWs[(c + 2) * HH + lane], y2);
        y3 = fmaf(__shfl_sync(0xffffffffu, xb, c + 3), sWs[(c + 3) * HH + lane], y3);
    }
    g_y[i] = (y0 + y1) + (y2 + y3);
}

// ---------------------------------------------------------------------------
// Kernel 2: fused scan — per-tile exclusive scan, then last block scans tiles
// ---------------------------------------------------------------------------
__global__ void scan_kernel() {
    __shared__ unsigned a[256], b[256];
    int idx = blockIdx.x * 256 + threadIdx.x;
    unsigned v = g_cnt[idx];
    a[threadIdx.x] = v;
    __syncthreads();
    unsigned* s = a; unsigned* d = b;
    for (int o = 1; o < 256; o <<= 1) {
        unsigned t = s[threadIdx.x];
        if (threadIdx.x >= o) t += s[threadIdx.x - o];
        d[threadIdx.x] = t;
        __syncthreads();
        unsigned* tmp = s; s = d; d = tmp;
    }
    unsigned excl = s[threadIdx.x] - v;
    g_rowloc[idx] = excl;
    if (idx < NN) g_cursor[idx] = excl;
    if (threadIdx.x == 255) g_bsum[blockIdx.x] = s[255];

    __shared__ bool isLast;
    __syncthreads();
    if (threadIdx.x == 0) {
        __threadfence();
        isLast = (atomicAdd(&g_scansem, 1u) == (unsigned)(TILES - 1));
    }
    __syncthreads();
    if (isLast) {
        __threadfence();
        unsigned w = (threadIdx.x < TILES) ? g_bsum[threadIdx.x] : 0u;
        a[threadIdx.x] = w;
        __syncthreads();
        s = a; d = b;
        for (int o = 1; o < 256; o <<= 1) {
            unsigned t = s[threadIdx.x];
            if (threadIdx.x >= o) t += s[threadIdx.x - o];
            d[threadIdx.x] = t;
            __syncthreads();
            unsigned* tmp = s; s = d; d = tmp;
        }
        g_tileoff[threadIdx.x] = s[threadIdx.x] - w;
        if (threadIdx.x == 0) g_scansem = 0u;
    }
}

// ---------------------------------------------------------------------------
// Kernel 3: reorder edges into dst buckets (2 edges per thread for ILP)
// ---------------------------------------------------------------------------
#define HALF_E (EE / 2)
__global__ __launch_bounds__(256)
void reorder_kernel(const int* __restrict__ edge_index,
                    const float* __restrict__ edge_weight) {
    int e = blockIdx.x * blockDim.x + threadIdx.x;
    if (e >= HALF_E) return;
    int e2 = e + HALF_E;

    int s1 = edge_index[e];
    int d1 = edge_index[EE + e];
    float w1 = edge_weight[e];
    int s2 = edge_index[e2];
    int d2 = edge_index[EE + e2];
    float w2 = edge_weight[e2];

    unsigned p1 = g_tileoff[d1 >> 8] + atomicAdd(&g_cursor[d1], 1u);
    unsigned p2 = g_tileoff[d2 >> 8] + atomicAdd(&g_cursor[d2], 1u);
    g_edges[p1] = make_uint2((unsigned)s1, __float_as_uint(w1));
    g_edges[p2] = make_uint2((unsigned)s2, __float_as_uint(w2));
}

__device__ __forceinline__ unsigned row_start(int m) {
    return g_tileoff[m >> 8] + g_rowloc[m];
}

// ---------------------------------------------------------------------------
// Kernel 4: fused pipelined CSR gather + fc1 GEMV + head + cleanup
// ---------------------------------------------------------------------------
__device__ __forceinline__ float gather_node(int n, int nmax, const float* sW0) {
    const int lane = threadIdx.x & 31;
    float ra = 0.f, rb = 0.f;
    if (n < nmax) {
        unsigned beg = row_start(n);
        unsigned end = row_start(n + 1);
        for (unsigned j = beg; j < end; j += 32) {
            bool inr = (j + (unsigned)lane < end);
            uint2 ed = inr ? g_edges[j + lane] : make_uint2(0u, 0u);
            float wgt = inr ? __uint_as_float(ed.y) : 0.f;

            unsigned slm = __ballot_sync(0xffffffffu, inr && ed.x == (unsigned)n);
            if (slm) {    // rare self-loop(s): k=0 identity term, weight 1 each
                float cnt = (float)__popc(slm);
                float xc = g_xbn[(size_t)n * CC + lane];
                float s0 = 0.f;
#pragma unroll
                for (int c = 0; c < CC; c++)
                    s0 = fmaf(__shfl_sync(0xffffffffu, xc, c), sW0[c * HH + lane], s0);
                ra = fmaf(cnt, s0, ra);
            }
#pragma unroll
            for (int i = 0; i < 32; i += 2) {
                float wa = __shfl_sync(0xffffffffu, wgt, i);
                unsigned sa = __shfl_sync(0xffffffffu, ed.x, i);
                float wb = __shfl_sync(0xffffffffu, wgt, i + 1);
                unsigned sb = __shfl_sync(0xffffffffu, ed.x, i + 1);
                ra = fmaf(wa, g_y[(size_t)sa * HH + lane], ra);
                rb = fmaf(wb, g_y[(size_t)sb * HH + lane], rb);
            }
        }
    }
    return fmaxf(ra + rb, 0.f);
}

__global__ __launch_bounds__(256, 3)
void fused_kernel(const float* __restrict__ W,       // W[0] block for self-loops
                  const float* __restrict__ fc1_w,
                  const float* __restrict__ fc1_b,
                  const float* __restrict__ fc2_w,
                  const float* __restrict__ fc2_b,
                  float* __restrict__ out) {
    __shared__ float sW0[CC * HH];
    __shared__ float sres[2][512];       // 16 nodes x 32 per buffer
    __shared__ float sAcc[FC];
    for (int i = threadIdx.x; i < CC * HH; i += 256) sW0[i] = W[i];
    if (threadIdx.x < FC) sAcc[threadIdx.x] = 0.f;

    // zero histogram for the NEXT replay (cnt already consumed by scan)
    for (int idx = blockIdx.x * 256 + threadIdx.x; idx < CNTSZ; idx += FGRID * 256)
        g_cnt[idx] = 0u;
    __syncthreads();

    const int tid  = threadIdx.x;
    const int w    = tid >> 5;
    const int lane = tid & 31;
    const int gfc  = tid >> 6;        // f-group 0..3 (16 f's each)
    const int i4   = tid & 63;        // float4 slot within a 64-slot half-tile
    const int nbeg = blockIdx.x * NPB;
    const int nend = min(nbeg + NPB, NN);
    const int nt   = (nend - nbeg + 15) >> 4;   // 16-node tiles in this block

    float acc[16];
#pragma unroll
    for (int k = 0; k < 16; k++) acc[k] = 0.f;

    const float4* W4 = reinterpret_cast<const float4*>(fc1_w);

    // prologue: gather tile 0 (each warp: 2 nodes)
    sres[0][w * 32 + lane]       = gather_node(nbeg + w, nend, sW0);
    sres[0][(w + 8) * 32 + lane] = gather_node(nbeg + 8 + w, nend, sW0);
    __syncthreads();

    for (int t = 0; t < nt; t++) {
        int cur = t & 1;
        // gather tile t+1 FIRST (its L2 latency hides under gemv DRAM stream)
        float rn0 = 0.f, rn1 = 0.f;
        if (t + 1 < nt) {
            int b = nbeg + (t + 1) * 16;
            rn0 = gather_node(b + w, nend, sW0);
            rn1 = gather_node(b + 8 + w, nend, sW0);
        }

        // gemv over tile t: 2 passes of 64 float4 slots
        int t0 = nbeg + t * 16;
        int nv4 = (min(t0 + 16, nend) - t0) * 8;    // valid float4 slots
        const float4* R4 = reinterpret_cast<const float4*>(sres[cur]);
#pragma unroll
        for (int p = 0; p < 2; p++) {
            int slot = i4 + p * 64;
            if (slot < nv4) {
                float4 rv = R4[slot];
                size_t base = (size_t)t0 * 8 + slot;
#pragma unroll
                for (int k = 0; k < 16; k++) {
                    int f = gfc * 16 + k;
                    float4 wv = __ldcs(W4 + (size_t)f * NH4 + base);
                    acc[k] = fmaf(rv.x, wv.x, acc[k]);
                    acc[k] = fmaf(rv.y, wv.y, acc[k]);
                    acc[k] = fmaf(rv.z, wv.z, acc[k]);
                    acc[k] = fmaf(rv.w, wv.w, acc[k]);
                }
            }
        }
        sres[1 - cur][w * 32 + lane]       = rn0;
        sres[1 - cur][(w + 8) * 32 + lane] = rn1;
        __syncthreads();
    }

    // block reduction
#pragma unroll
    for (int k = 0; k < 16; k++) {
        float v = acc[k];
        v += __shfl_xor_sync(0xffffffffu, v, 16);
        v += __shfl_xor_sync(0xffffffffu, v, 8);
        v += __shfl_xor_sync(0xffffffffu, v, 4);
        v += __shfl_xor_sync(0xffffffffu, v, 2);
        v += __shfl_xor_sync(0xffffffffu, v, 1);
        if (lane == 0) atomicAdd(&sAcc[gfc * 16 + k], v);
    }
    __syncthreads();
    if (tid < FC) atomicAdd(&g_hacc[tid], sAcc[tid]);
    __syncthreads();

    // last block: head + cleanup
    __shared__ bool isLast;
    if (tid == 0) {
        __threadfence();
        isLast = (atomicAdd(&g_sem, 1u) == (unsigned)(FGRID - 1));
    }
    __syncthreads();
    if (isLast) {
        __threadfence();
        __shared__ float hv[FC];
        volatile float* vh = g_hacc;
        if (tid < FC) hv[tid] = fmaxf(vh[tid] + fc1_b[tid], 0.f);
        __syncthreads();
        if (tid < NCLS) {
            float s = fc2_b[tid];
#pragma unroll
            for (int f = 0; f < FC; f++)
                s = fmaf(hv[f], fc2_w[tid * FC + f], s);
            out[tid] = s;
        }
        __syncthreads();
        if (tid < FC) g_hacc[tid] = 0.f;
        if (tid == 0) g_sem = 0u;
    }
}

// ---------------------------------------------------------------------------
// launch
// ---------------------------------------------------------------------------
extern "C" void kernel_launch(void* const* d_in, const int* in_sizes, int n_in,
                              void* d_out, int out_size) {
    const float* x        = (const float*)d_in[0];
    const float* ew       = (const float*)d_in[1];
    const float* W        = (const float*)d_in[2];
    const float* bn_gamma = (const float*)d_in[3];
    const float* bn_beta  = (const float*)d_in[4];
    const float* bn_mean  = (const float*)d_in[5];
    const float* bn_var   = (const float*)d_in[6];
    const float* fc1_w    = (const float*)d_in[7];
    const float* fc1_b    = (const float*)d_in[8];
    const float* fc2_w    = (const float*)d_in[9];
    const float* fc2_b    = (const float*)d_in[10];
    const int*   ei       = (const int*)d_in[11];
    float* out            = (float*)d_out;

    prep_kernel<<<(NN * CC) / 256, 256>>>(x, bn_gamma, bn_beta, bn_mean, bn_var, W, ei);
    scan_kernel<<<TILES, 256>>>();
    reorder_kernel<<<(HALF_E + 255) / 256, 256>>>(ei, ew);
    fused_kernel<<<FGRID, 256>>>(W, fc1_w, fc1_b, fc2_w, fc2_b, out);
}

// round 8
// speedup vs baseline: 1.1852x; 1.1852x over previous
#include <cuda_runtime.h>

// Problem constants (fixed shapes)
#define NN      50000
#define CC      32
#define HH      32
#define EE      1600000      // == NN*CC (exploited in prep)
#define NH      1600000
#define NH4     400000
#define FC      64
#define NCLS    2
#define BN_EPS  1e-5f

#define TILES   196          // ceil(NN/256)
#define CNTSZ   (TILES * 256)
#define NPB     96           // nodes per block (multiple of 8)
#define FGRID   521          // ceil(NN/NPB)

// Scratch (device globals; all zero at module load)
__device__ __align__(16) float g_xbn[NN * CC];
__device__ __align__(16) float g_y[NN * HH];
__device__ __align__(16) uint2 g_edges[EE];
__device__ unsigned g_cnt[CNTSZ];       // dst histogram (zeroed by fused tail)
__device__ unsigned g_rowloc[CNTSZ];    // per-tile-local exclusive offsets
__device__ unsigned g_cursor[NN];
__device__ unsigned g_bsum[256];
__device__ unsigned g_tileoff[256];
__device__ float g_hacc[FC];            // zeroed by fused tail
__device__ unsigned g_sem;              // zeroed by fused tail
__device__ unsigned g_scansem;          // zeroed by scan tail

// ---------------------------------------------------------------------------
// Kernel 1: BN + projection y = bn(x) @ (W1+W2) + dst histogram
// ---------------------------------------------------------------------------
__global__ __launch_bounds__(256)
void prep_kernel(const float* __restrict__ x,
                 const float* __restrict__ gamma,
                 const float* __restrict__ beta,
                 const float* __restrict__ mean,
                 const float* __restrict__ var,
                 const float* __restrict__ W,
                 const int*   __restrict__ edge_index) {
    __shared__ float sWs[CC * HH];
    for (int i = threadIdx.x; i < CC * HH; i += 256)
        sWs[i] = W[CC * HH + i] + W[2 * CC * HH + i];
    __syncthreads();

    int i = blockIdx.x * 256 + threadIdx.x;       // exactly 1.6M threads
    int lane = i & 31;

    // histogram (thread i handles edge i; EE == NN*CC)
    atomicAdd(&g_cnt[edge_index[EE + i]], 1u);

    float xv = x[i];
    float s = rsqrtf(var[lane] + BN_EPS) * gamma[lane];
    float xb = (xv - mean[lane]) * s + beta[lane];
    g_xbn[i] = xb;

    float y0 = 0.f, y1 = 0.f, y2 = 0.f, y3 = 0.f;
#pragma unroll
    for (int c = 0; c < CC; c += 4) {
        y0 = fmaf(__shfl_sync(0xffffffffu, xb, c    ), sWs[(c    ) * HH + lane], y0);
        y1 = fmaf(__shfl_sync(0xffffffffu, xb, c + 1), sWs[(c + 1) * HH + lane], y1);
        y2 = fmaf(__shfl_sync(0xffffffffu, xb, c + 2), sWs[(c + 2) * HH + lane], y2);
        y3 = fmaf(__shfl_sync(0xffffffffu, xb, c + 3), sWs[(c + 3) * HH + lane], y3);
    }
    g_y[i] = (y0 + y1) + (y2 + y3);
}

// ---------------------------------------------------------------------------
// Kernel 2: fused scan — per-tile exclusive scan, then last block scans tiles
// ---------------------------------------------------------------------------
__global__ void scan_kernel() {
    __shared__ unsigned a[256], b[256];
    int idx = blockIdx.x * 256 + threadIdx.x;
    unsigned v = g_cnt[idx];
    a[threadIdx.x] = v;
    __syncthreads();
    unsigned* s = a; unsigned* d = b;
    for (int o = 1; o < 256; o <<= 1) {
        unsigned t = s[threadIdx.x];
        if (threadIdx.x >= o) t += s[threadIdx.x - o];
        d[threadIdx.x] = t;
        __syncthreads();
        unsigned* tmp = s; s = d; d = tmp;
    }
    unsigned excl = s[threadIdx.x] - v;
    g_rowloc[idx] = excl;
    if (idx < NN) g_cursor[idx] = excl;
    if (threadIdx.x == 255) g_bsum[blockIdx.x] = s[255];

    __shared__ bool isLast;
    __syncthreads();
    if (threadIdx.x == 0) {
        __threadfence();
        isLast = (atomicAdd(&g_scansem, 1u) == (unsigned)(TILES - 1));
    }
    __syncthreads();
    if (isLast) {
        __threadfence();
        unsigned w = (threadIdx.x < TILES) ? g_bsum[threadIdx.x] : 0u;
        a[threadIdx.x] = w;
        __syncthreads();
        s = a; d = b;
        for (int o = 1; o < 256; o <<= 1) {
            unsigned t = s[threadIdx.x];
            if (threadIdx.x >= o) t += s[threadIdx.x - o];
            d[threadIdx.x] = t;
            __syncthreads();
            unsigned* tmp = s; s = d; d = tmp;
        }
        g_tileoff[threadIdx.x] = s[threadIdx.x] - w;
        if (threadIdx.x == 0) g_scansem = 0u;
    }
}

// ---------------------------------------------------------------------------
// Kernel 3: reorder edges into dst buckets (4 edges per thread for atomic MLP)
// ---------------------------------------------------------------------------
#define QE (EE / 4)
__global__ __launch_bounds__(256)
void reorder_kernel(const int* __restrict__ edge_index,
                    const float* __restrict__ edge_weight) {
    int e = blockIdx.x * blockDim.x + threadIdx.x;
    if (e >= QE) return;

    int s0 = edge_index[e];
    int s1 = edge_index[e + QE];
    int s2 = edge_index[e + 2 * QE];
    int s3 = edge_index[e + 3 * QE];
    int d0 = edge_index[EE + e];
    int d1 = edge_index[EE + e + QE];
    int d2 = edge_index[EE + e + 2 * QE];
    int d3 = edge_index[EE + e + 3 * QE];
    float w0 = edge_weight[e];
    float w1 = edge_weight[e + QE];
    float w2 = edge_weight[e + 2 * QE];
    float w3 = edge_weight[e + 3 * QE];

    unsigned p0 = g_tileoff[d0 >> 8] + atomicAdd(&g_cursor[d0], 1u);
    unsigned p1 = g_tileoff[d1 >> 8] + atomicAdd(&g_cursor[d1], 1u);
    unsigned p2 = g_tileoff[d2 >> 8] + atomicAdd(&g_cursor[d2], 1u);
    unsigned p3 = g_tileoff[d3 >> 8] + atomicAdd(&g_cursor[d3], 1u);
    g_edges[p0] = make_uint2((unsigned)s0, __float_as_uint(w0));
    g_edges[p1] = make_uint2((unsigned)s1, __float_as_uint(w1));
    g_edges[p2] = make_uint2((unsigned)s2, __float_as_uint(w2));
    g_edges[p3] = make_uint2((unsigned)s3, __float_as_uint(w3));
}

__device__ __forceinline__ unsigned row_start(int m) {
    return g_tileoff[m >> 8] + g_rowloc[m];
}

// ---------------------------------------------------------------------------
// Kernel 4: warp-specialized fused CSR gather + fc1 GEMV + head + cleanup
//   warps 0-3: consumers (pure fc1_w DRAM streaming)
//   warps 4-7: producers (CSR gather into next sres buffer)
// ---------------------------------------------------------------------------
__device__ __forceinline__ float gather_node(int n, int nmax, const float* sW0) {
    const int lane = threadIdx.x & 31;
    float ra = 0.f, rb = 0.f;
    if (n < nmax) {
        unsigned beg = row_start(n);
        unsigned end = row_start(n + 1);
        for (unsigned j = beg; j < end; j += 32) {
            bool inr = (j + (unsigned)lane < end);
            uint2 ed = inr ? g_edges[j + lane] : make_uint2(0u, 0u);
            float wgt = inr ? __uint_as_float(ed.y) : 0.f;

            unsigned slm = __ballot_sync(0xffffffffu, inr && ed.x == (unsigned)n);
            if (slm) {    // rare self-loop(s): k=0 identity term, weight 1 each
                float cnt = (float)__popc(slm);
                float xc = g_xbn[(size_t)n * CC + lane];
                float s0 = 0.f;
#pragma unroll
                for (int c = 0; c < CC; c++)
                    s0 = fmaf(__shfl_sync(0xffffffffu, xc, c), sW0[c * HH + lane], s0);
                ra = fmaf(cnt, s0, ra);
            }
#pragma unroll
            for (int i = 0; i < 32; i += 2) {
                float wa = __shfl_sync(0xffffffffu, wgt, i);
                unsigned sa = __shfl_sync(0xffffffffu, ed.x, i);
                float wb = __shfl_sync(0xffffffffu, wgt, i + 1);
                unsigned sb = __shfl_sync(0xffffffffu, ed.x, i + 1);
                ra = fmaf(wa, g_y[(size_t)sa * HH + lane], ra);
                rb = fmaf(wb, g_y[(size_t)sb * HH + lane], rb);
            }
        }
    }
    return fmaxf(ra + rb, 0.f);
}

__global__ __launch_bounds__(256, 2)
void fused_kernel(const float* __restrict__ W,       // W[0] block for self-loops
                  const float* __restrict__ fc1_w,
                  const float* __restrict__ fc1_b,
                  const float* __restrict__ fc2_w,
                  const float* __restrict__ fc2_b,
                  float* __restrict__ out) {
    __shared__ float sW0[CC * HH];
    __shared__ float sres[2][256];       // 8 nodes x 32 per buffer
    __shared__ float sAcc[FC];
    for (int i = threadIdx.x; i < CC * HH; i += 256) sW0[i] = W[i];
    if (threadIdx.x < FC) sAcc[threadIdx.x] = 0.f;

    // zero histogram for the NEXT replay (cnt already consumed by scan)
    for (int idx = blockIdx.x * 256 + threadIdx.x; idx < CNTSZ; idx += FGRID * 256)
        g_cnt[idx] = 0u;

    const int tid  = threadIdx.x;
    const int w    = tid >> 5;
    const int lane = tid & 31;
    const bool producer = (w >= 4);
    const int pw   = w - 4;           // producer warp id 0..3
    const int nbeg = blockIdx.x * NPB;
    const int nend = min(nbeg + NPB, NN);
    const int nt   = (nend - nbeg + 7) >> 3;   // 8-node tiles in this block

    float acc[16];
#pragma unroll
    for (int k = 0; k < 16; k++) acc[k] = 0.f;

    const float4* W4 = reinterpret_cast<const float4*>(fc1_w);
    const int gfc = tid >> 5;         // consumer f-group 0..3 (warps 0-3)

    // prologue: producers gather tile 0 (2 nodes per producer warp)
    if (producer) {
        sres[0][pw * 32 + lane]       = gather_node(nbeg + pw, nend, sW0);
        sres[0][(pw + 4) * 32 + lane] = gather_node(nbeg + 4 + pw, nend, sW0);
    }
    __syncthreads();

    for (int t = 0; t < nt; t++) {
        int cur = t & 1;
        if (producer) {
            // gather tile t+1 into the other buffer
            if (t + 1 < nt) {
                int b = nbeg + (t + 1) * 8;
                float r0 = gather_node(b + pw, nend, sW0);
                float r1 = gather_node(b + 4 + pw, nend, sW0);
                sres[1 - cur][pw * 32 + lane]       = r0;
                sres[1 - cur][(pw + 4) * 32 + lane] = r1;
            }
        } else {
            // consumer: stream fc1_w for tile t (2 slots x 16 f's)
            int t0 = nbeg + t * 8;
            int nv4 = (min(t0 + 8, nend) - t0) * 8;   // valid float4 slots (<=64)
            const float4* R4 = reinterpret_cast<const float4*>(sres[cur]);
#pragma unroll
            for (int p = 0; p < 2; p++) {
                int slot = lane + p * 32;
                if (slot < nv4) {
                    float4 rv = R4[slot];
                    size_t base = (size_t)t0 * 8 + slot;
#pragma unroll
                    for (int k = 0; k < 16; k++) {
                        int f = gfc * 16 + k;
                        float4 wv = __ldcs(W4 + (size_t)f * NH4 + base);
                        acc[k] = fmaf(rv.x, wv.x, acc[k]);
                        acc[k] = fmaf(rv.y, wv.y, acc[k]);
                        acc[k] = fmaf(rv.z, wv.z, acc[k]);
                        acc[k] = fmaf(rv.w, wv.w, acc[k]);
                    }
                }
            }
        }
        __syncthreads();
    }

    // consumer warp reduction: warp gfc owns f-range [gfc*16, gfc*16+16)
    if (!producer) {
#pragma unroll
        for (int k = 0; k < 16; k++) {
            float v = acc[k];
            v += __shfl_xor_sync(0xffffffffu, v, 16);
            v += __shfl_xor_sync(0xffffffffu, v, 8);
            v += __shfl_xor_sync(0xffffffffu, v, 4);
            v += __shfl_xor_sync(0xffffffffu, v, 2);
            v += __shfl_xor_sync(0xffffffffu, v, 1);
            if (lane == 0) sAcc[gfc * 16 + k] = v;
        }
    }
    __syncthreads();
    if (tid < FC) atomicAdd(&g_hacc[tid], sAcc[tid]);
    __syncthreads();

    // last block: head + cleanup
    __shared__ bool isLast;
    if (tid == 0) {
        __threadfence();
        isLast = (atomicAdd(&g_sem, 1u) == (unsigned)(FGRID - 1));
    }
    __syncthreads();
    if (isLast) {
        __threadfence();
        __shared__ float hv[FC];
        volatile float* vh = g_hacc;
        if (tid < FC) hv[tid] = fmaxf(vh[tid] + fc1_b[tid], 0.f);
        __syncthreads();
        if (tid < NCLS) {
            float s = fc2_b[tid];
#pragma unroll
            for (int f = 0; f < FC; f++)
                s = fmaf(hv[f], fc2_w[tid * FC + f], s);
            out[tid] = s;
        }
        __syncthreads();
        if (tid < FC) g_hacc[tid] = 0.f;
        if (tid == 0) g_sem = 0u;
    }
}

// ---------------------------------------------------------------------------
// launch
// ---------------------------------------------------------------------------
extern "C" void kernel_launch(void* const* d_in, const int* in_sizes, int n_in,
                              void* d_out, int out_size) {
    const float* x        = (const float*)d_in[0];
    const float* ew       = (const float*)d_in[1];
    const float* W        = (const float*)d_in[2];
    const float* bn_gamma = (const float*)d_in[3];
    const float* bn_beta  = (const float*)d_in[4];
    const float* bn_mean  = (const float*)d_in[5];
    const float* bn_var   = (const float*)d_in[6];
    const float* fc1_w    = (const float*)d_in[7];
    const float* fc1_b    = (const float*)d_in[8];
    const float* fc2_w    = (const float*)d_in[9];
    const float* fc2_b    = (const float*)d_in[10];
    const int*   ei       = (const int*)d_in[11];
    float* out            = (float*)d_out;

    prep_kernel<<<(NN * CC) / 256, 256>>>(x, bn_gamma, bn_beta, bn_mean, bn_var, W, ei);
    scan_kernel<<<TILES, 256>>>();
    reorder_kernel<<<(QE + 255) / 256, 256>>>(ei, ew);
    fused_kernel<<<FGRID, 256>>>(W, fc1_w, fc1_b, fc2_w, fc2_b, out);
}

// round 9
// speedup vs baseline: 1.2636x; 1.0661x over previous
#include <cuda_runtime.h>

// Problem constants (fixed shapes)
#define NN      50000
#define CC      32
#define HH      32
#define EE      1600000      // == NN*CC (exploited in prep)
#define NH      1600000
#define NH4     400000
#define FC      64
#define NCLS    2
#define BN_EPS  1e-5f

#define TILES   196          // ceil(NN/256)
#define CNTSZ   (TILES * 256)
#define NPB     176          // nodes per block (multiple of 16)
#define FGRID   285          // ceil(NN/NPB) ~= one wave at 2 CTAs/SM

// Scratch (device globals; all zero at module load)
__device__ __align__(16) float g_xbn[NN * CC];
__device__ __align__(16) float g_y[NN * HH];
__device__ __align__(16) uint2 g_edges[EE];
__device__ unsigned g_cnt[CNTSZ];       // dst histogram (zeroed by fused tail)
__device__ unsigned g_rowloc[CNTSZ];    // per-tile-local exclusive offsets
__device__ unsigned g_cursor[NN];
__device__ unsigned g_bsum[256];
__device__ unsigned g_tileoff[256];
__device__ float g_hacc[FC];            // zeroed by fused tail
__device__ unsigned g_sem;              // zeroed by fused tail
__device__ unsigned g_scansem;          // zeroed by scan tail

// ---------------------------------------------------------------------------
// Kernel 1: BN + projection y = bn(x) @ (W1+W2) + dst histogram
// ---------------------------------------------------------------------------
__global__ __launch_bounds__(256)
void prep_kernel(const float* __restrict__ x,
                 const float* __restrict__ gamma,
                 const float* __restrict__ beta,
                 const float* __restrict__ mean,
                 const float* __restrict__ var,
                 const float* __restrict__ W,
                 const int*   __restrict__ edge_index) {
    __shared__ float sWs[CC * HH];
    for (int i = threadIdx.x; i < CC * HH; i += 256)
        sWs[i] = W[CC * HH + i] + W[2 * CC * HH + i];
    __syncthreads();

    int i = blockIdx.x * 256 + threadIdx.x;       // exactly 1.6M threads
    int lane = i & 31;

    // histogram (thread i handles edge i; EE == NN*CC)
    atomicAdd(&g_cnt[edge_index[EE + i]], 1u);

    float xv = x[i];
    float s = rsqrtf(var[lane] + BN_EPS) * gamma[lane];
    float xb = (xv - mean[lane]) * s + beta[lane];
    g_xbn[i] = xb;

    float y0 = 0.f, y1 = 0.f, y2 = 0.f, y3 = 0.f;
#pragma unroll
    for (int c = 0; c < CC; c += 4) {
        y0 = fmaf(__shfl_sync(0xffffffffu, xb, c    ), sWs[(c    ) * HH + lane], y0);
        y1 = fmaf(__shfl_sync(0xffffffffu, xb, c + 1), sWs[(c + 1) * HH + lane], y1);
        y2 = fmaf(__shfl_sync(0xffffffffu, xb, c + 2), sWs[(c + 2) * HH + lane], y2);
        y3 = fmaf(__shfl_sync(0xffffffffu, xb, c + 3), sWs[(c + 3) * HH + lane], y3);
    }
    g_y[i] = (y0 + y1) + (y2 + y3);
}

// ---------------------------------------------------------------------------
// Kernel 2: fused scan — per-tile exclusive scan, then last block scans tiles
// ---------------------------------------------------------------------------
__global__ void scan_kernel() {
    __shared__ unsigned a[256], b[256];
    int idx = blockIdx.x * 256 + threadIdx.x;
    unsigned v = g_cnt[idx];
    a[threadIdx.x] = v;
    __syncthreads();
    unsigned* s = a; unsigned* d = b;
    for (int o = 1; o < 256; o <<= 1) {
        unsigned t = s[threadIdx.x];
        if (threadIdx.x >= o) t += s[threadIdx.x - o];
        d[threadIdx.x] = t;
        __syncthreads();
        unsigned* tmp = s; s = d; d = tmp;
    }
    unsigned excl = s[threadIdx.x] - v;
    g_rowloc[idx] = excl;
    if (idx < NN) g_cursor[idx] = excl;
    if (threadIdx.x == 255) g_bsum[blockIdx.x] = s[255];

    __shared__ bool isLast;
    __syncthreads();
    if (threadIdx.x == 0) {
        __threadfence();
        isLast = (atomicAdd(&g_scansem, 1u) == (unsigned)(TILES - 1));
    }
    __syncthreads();
    if (isLast) {
        __threadfence();
        unsigned w = (threadIdx.x < TILES) ? g_bsum[threadIdx.x] : 0u;
        a[threadIdx.x] = w;
        __syncthreads();
        s = a; d = b;
        for (int o = 1; o < 256; o <<= 1) {
            unsigned t = s[threadIdx.x];
            if (threadIdx.x >= o) t += s[threadIdx.x - o];
            d[threadIdx.x] = t;
            __syncthreads();
            unsigned* tmp = s; s = d; d = tmp;
        }
        g_tileoff[threadIdx.x] = s[threadIdx.x] - w;
        if (threadIdx.x == 0) g_scansem = 0u;
    }
}

// ---------------------------------------------------------------------------
// Kernel 3: reorder edges into dst buckets (4 edges per thread for atomic MLP)
// ---------------------------------------------------------------------------
#define QE (EE / 4)
__global__ __launch_bounds__(256)
void reorder_kernel(const int* __restrict__ edge_index,
                    const float* __restrict__ edge_weight) {
    int e = blockIdx.x * blockDim.x + threadIdx.x;
    if (e >= QE) return;

    int s0 = edge_index[e];
    int s1 = edge_index[e + QE];
    int s2 = edge_index[e + 2 * QE];
    int s3 = edge_index[e + 3 * QE];
    int d0 = edge_index[EE + e];
    int d1 = edge_index[EE + e + QE];
    int d2 = edge_index[EE + e + 2 * QE];
    int d3 = edge_index[EE + e + 3 * QE];
    float w0 = edge_weight[e];
    float w1 = edge_weight[e + QE];
    float w2 = edge_weight[e + 2 * QE];
    float w3 = edge_weight[e + 3 * QE];

    unsigned p0 = g_tileoff[d0 >> 8] + atomicAdd(&g_cursor[d0], 1u);
    unsigned p1 = g_tileoff[d1 >> 8] + atomicAdd(&g_cursor[d1], 1u);
    unsigned p2 = g_tileoff[d2 >> 8] + atomicAdd(&g_cursor[d2], 1u);
    unsigned p3 = g_tileoff[d3 >> 8] + atomicAdd(&g_cursor[d3], 1u);
    g_edges[p0] = make_uint2((unsigned)s0, __float_as_uint(w0));
    g_edges[p1] = make_uint2((unsigned)s1, __float_as_uint(w1));
    g_edges[p2] = make_uint2((unsigned)s2, __float_as_uint(w2));
    g_edges[p3] = make_uint2((unsigned)s3, __float_as_uint(w3));
}

__device__ __forceinline__ unsigned row_start(int m) {
    return g_tileoff[m >> 8] + g_rowloc[m];
}

// ---------------------------------------------------------------------------
// Interleaved dual-node gather: both rows' loads in flight simultaneously.
// ---------------------------------------------------------------------------
__device__ __forceinline__ void gather_node2(int n0, int n1, int nmax,
                                             const float* sW0,
                                             float& out0, float& out1) {
    const int lane = threadIdx.x & 31;
    unsigned j0 = 0, e0 = 0, j1 = 0, e1 = 0;
    if (n0 < nmax) { j0 = row_start(n0); e0 = row_start(n0 + 1); }
    if (n1 < nmax) { j1 = row_start(n1); e1 = row_start(n1 + 1); }

    float a0 = 0.f, b0 = 0.f, a1 = 0.f, b1 = 0.f;
    while (j0 < e0 || j1 < e1) {
        bool in0 = (j0 + (unsigned)lane < e0);
        bool in1 = (j1 + (unsigned)lane < e1);
        uint2 ed0 = in0 ? g_edges[j0 + lane] : make_uint2(0u, 0u);
        uint2 ed1 = in1 ? g_edges[j1 + lane] : make_uint2(0u, 0u);
        float w0 = in0 ? __uint_as_float(ed0.y) : 0.f;
        float w1 = in1 ? __uint_as_float(ed1.y) : 0.f;

        // rare self-loop(s): k=0 identity term, weight 1 each
        unsigned sl0 = __ballot_sync(0xffffffffu, in0 && ed0.x == (unsigned)n0);
        unsigned sl1 = __ballot_sync(0xffffffffu, in1 && ed1.x == (unsigned)n1);
        if (sl0) {
            float cnt = (float)__popc(sl0);
            float xc = g_xbn[(size_t)n0 * CC + lane];
            float s0 = 0.f;
#pragma unroll
            for (int c = 0; c < CC; c++)
                s0 = fmaf(__shfl_sync(0xffffffffu, xc, c), sW0[c * HH + lane], s0);
            a0 = fmaf(cnt, s0, a0);
        }
        if (sl1) {
            float cnt = (float)__popc(sl1);
            float xc = g_xbn[(size_t)n1 * CC + lane];
            float s1 = 0.f;
#pragma unroll
            for (int c = 0; c < CC; c++)
                s1 = fmaf(__shfl_sync(0xffffffffu, xc, c), sW0[c * HH + lane], s1);
            a1 = fmaf(cnt, s1, a1);
        }

#pragma unroll
        for (int i = 0; i < 32; i += 2) {
            float    wa0 = __shfl_sync(0xffffffffu, w0, i);
            unsigned sa0 = __shfl_sync(0xffffffffu, ed0.x, i);
            float    wb0 = __shfl_sync(0xffffffffu, w0, i + 1);
            unsigned sb0 = __shfl_sync(0xffffffffu, ed0.x, i + 1);
            float    wa1 = __shfl_sync(0xffffffffu, w1, i);
            unsigned sa1 = __shfl_sync(0xffffffffu, ed1.x, i);
            float    wb1 = __shfl_sync(0xffffffffu, w1, i + 1);
            unsigned sb1 = __shfl_sync(0xffffffffu, ed1.x, i + 1);
            a0 = fmaf(wa0, g_y[(size_t)sa0 * HH + lane], a0);
            b0 = fmaf(wb0, g_y[(size_t)sb0 * HH + lane], b0);
            a1 = fmaf(wa1, g_y[(size_t)sa1 * HH + lane], a1);
            b1 = fmaf(wb1, g_y[(size_t)sb1 * HH + lane], b1);
        }
        if (j0 < e0) j0 += 32;
        if (j1 < e1) j1 += 32;
    }
    out0 = fmaxf(a0 + b0, 0.f);
    out1 = fmaxf(a1 + b1, 0.f);
}

// ---------------------------------------------------------------------------
// Kernel 4: fused pipelined CSR gather + fc1 GEMV + head + cleanup
// all 8 warps: gather(t+1) then gemv(t); 16-node tiles, one barrier per tile
// ---------------------------------------------------------------------------
__global__ __launch_bounds__(256, 2)
void fused_kernel(const float* __restrict__ W,       // W[0] block for self-loops
                  const float* __restrict__ fc1_w,
                  const float* __restrict__ fc1_b,
                  const float* __restrict__ fc2_w,
                  const float* __restrict__ fc2_b,
                  float* __restrict__ out) {
    __shared__ float sW0[CC * HH];
    __shared__ float sres[2][512];       // 16 nodes x 32 per buffer
    __shared__ float sAcc[FC];
    for (int i = threadIdx.x; i < CC * HH; i += 256) sW0[i] = W[i];
    if (threadIdx.x < FC) sAcc[threadIdx.x] = 0.f;

    // zero histogram for the NEXT replay (cnt already consumed by scan)
    for (int idx = blockIdx.x * 256 + threadIdx.x; idx < CNTSZ; idx += FGRID * 256)
        g_cnt[idx] = 0u;
    __syncthreads();

    const int tid  = threadIdx.x;
    const int w    = tid >> 5;
    const int lane = tid & 31;
    const int gfc  = tid >> 6;        // f-group 0..3 (16 f's each)
    const int i4   = tid & 63;        // base float4 slot
    const int nbeg = blockIdx.x * NPB;
    const int nend = min(nbeg + NPB, NN);
    const int nt   = (nend - nbeg + 15) >> 4;   // 16-node tiles

    float acc[16];
#pragma unroll
    for (int k = 0; k < 16; k++) acc[k] = 0.f;

    const float4* W4 = reinterpret_cast<const float4*>(fc1_w);

    // prologue: gather tile 0 (each warp: nodes w and w+8, interleaved)
    {
        float r0, r1;
        gather_node2(nbeg + w, nbeg + 8 + w, nend, sW0, r0, r1);
        sres[0][w * 32 + lane]       = r0;
        sres[0][(w + 8) * 32 + lane] = r1;
    }
    __syncthreads();

    for (int t = 0; t < nt; t++) {
        int cur = t & 1;
        // gather tile t+1 FIRST (loads in flight while gemv streams)
        float rn0 = 0.f, rn1 = 0.f;
        if (t + 1 < nt) {
            int b = nbeg + (t + 1) * 16;
            gather_node2(b + w, b + 8 + w, nend, sW0, rn0, rn1);
        }

        // gemv over tile t: 2 passes of 64 float4 slots
        int t0 = nbeg + t * 16;
        int nv4 = (min(t0 + 16, nend) - t0) * 8;    // valid float4 slots
        const float4* R4 = reinterpret_cast<const float4*>(sres[cur]);
#pragma unroll
        for (int p = 0; p < 2; p++) {
            int slot = i4 + p * 64;
            if (slot < nv4) {
                float4 rv = R4[slot];
                size_t base = (size_t)t0 * 8 + slot;
#pragma unroll
                for (int k = 0; k < 16; k++) {
                    int f = gfc * 16 + k;
                    float4 wv = __ldcs(W4 + (size_t)f * NH4 + base);
                    acc[k] = fmaf(rv.x, wv.x, acc[k]);
                    acc[k] = fmaf(rv.y, wv.y, acc[k]);
                    acc[k] = fmaf(rv.z, wv.z, acc[k]);
                    acc[k] = fmaf(rv.w, wv.w, acc[k]);
                }
            }
        }
        sres[1 - cur][w * 32 + lane]       = rn0;
        sres[1 - cur][(w + 8) * 32 + lane] = rn1;
        __syncthreads();
    }

    // block reduction
#pragma unroll
    for (int k = 0; k < 16; k++) {
        float v = acc[k];
        v += __shfl_xor_sync(0xffffffffu, v, 16);
        v += __shfl_xor_sync(0xffffffffu, v, 8);
        v += __shfl_xor_sync(0xffffffffu, v, 4);
        v += __shfl_xor_sync(0xffffffffu, v, 2);
        v += __shfl_xor_sync(0xffffffffu, v, 1);
        if (lane == 0) atomicAdd(&sAcc[gfc * 16 + k], v);
    }
    __syncthreads();
    if (tid < FC) atomicAdd(&g_hacc[tid], sAcc[tid]);
    __syncthreads();

    // last block: head + cleanup
    __shared__ bool isLast;
    if (tid == 0) {
        __threadfence();
        isLast = (atomicAdd(&g_sem, 1u) == (unsigned)(FGRID - 1));
    }
    __syncthreads();
    if (isLast) {
        __threadfence();
        __shared__ float hv[FC];
        volatile float* vh = g_hacc;
        if (tid < FC) hv[tid] = fmaxf(vh[tid] + fc1_b[tid], 0.f);
        __syncthreads();
        if (tid < NCLS) {
            float s = fc2_b[tid];
#pragma unroll
            for (int f = 0; f < FC; f++)
                s = fmaf(hv[f], fc2_w[tid * FC + f], s);
            out[tid] = s;
        }
        __syncthreads();
        if (tid < FC) g_hacc[tid] = 0.f;
        if (tid == 0) g_sem = 0u;
    }
}

// ---------------------------------------------------------------------------
// launch
// ---------------------------------------------------------------------------
extern "C" void kernel_launch(void* const* d_in, const int* in_sizes, int n_in,
                              void* d_out, int out_size) {
    const float* x        = (const float*)d_in[0];
    const float* ew       = (const float*)d_in[1];
    const float* W        = (const float*)d_in[2];
    const float* bn_gamma = (const float*)d_in[3];
    const float* bn_beta  = (const float*)d_in[4];
    const float* bn_mean  = (const float*)d_in[5];
    const float* bn_var   = (const float*)d_in[6];
    const float* fc1_w    = (const float*)d_in[7];
    const float* fc1_b    = (const float*)d_in[8];
    const float* fc2_w    = (const float*)d_in[9];
    const float* fc2_b    = (const float*)d_in[10];
    const int*   ei       = (const int*)d_in[11];
    float* out            = (float*)d_out;

    prep_kernel<<<(NN * CC) / 256, 256>>>(x, bn_gamma, bn_beta, bn_mean, bn_var, W, ei);
    scan_kernel<<<TILES, 256>>>();
    reorder_kernel<<<(QE + 255) / 256, 256>>>(ei, ew);
    fused_kernel<<<FGRID, 256>>>(W, fc1_w, fc1_b, fc2_w, fc2_b, out);
}

// round 10
// speedup vs baseline: 1.3230x; 1.0470x over previous
#include <cuda_runtime.h>

// Problem constants (fixed shapes)
#define NN      50000
#define CC      32
#define HH      32
#define EE      1600000      // == NN*CC (exploited in prep)
#define NH      1600000
#define NH4     400000
#define FC      64
#define NCLS    2
#define BN_EPS  1e-5f

#define TILES   196          // ceil(NN/256)
#define CNTSZ   (TILES * 256)
#define NPB     88           // nodes per block (multiple of 8)
#define FGRID   569          // ceil(NN/NPB); 4 CTAs/SM x 148 SM = 592 slots
#define FBLK    128          // fused kernel block size

// Scratch (device globals; all zero at module load)
__device__ __align__(16) float g_xbn[NN * CC];
__device__ __align__(16) float g_y[NN * HH];
__device__ __align__(16) uint2 g_edges[EE];
__device__ unsigned g_cnt[CNTSZ];       // dst histogram (zeroed by fused tail)
__device__ unsigned g_rowloc[CNTSZ];    // per-tile-local exclusive offsets
__device__ unsigned g_cursor[NN];
__device__ unsigned g_bsum[256];
__device__ unsigned g_tileoff[256];
__device__ float g_hacc[FC];            // zeroed by fused tail
__device__ unsigned g_sem;              // zeroed by fused tail
__device__ unsigned g_scansem;          // zeroed by scan tail

// ---------------------------------------------------------------------------
// Kernel 1: BN + projection y = bn(x) @ (W1+W2) + dst histogram
// ---------------------------------------------------------------------------
__global__ __launch_bounds__(256)
void prep_kernel(const float* __restrict__ x,
                 const float* __restrict__ gamma,
                 const float* __restrict__ beta,
                 const float* __restrict__ mean,
                 const float* __restrict__ var,
                 const float* __restrict__ W,
                 const int*   __restrict__ edge_index) {
    __shared__ float sWs[CC * HH];
    for (int i = threadIdx.x; i < CC * HH; i += 256)
        sWs[i] = W[CC * HH + i] + W[2 * CC * HH + i];
    __syncthreads();

    int i = blockIdx.x * 256 + threadIdx.x;       // exactly 1.6M threads
    int lane = i & 31;

    // histogram (thread i handles edge i; EE == NN*CC)
    atomicAdd(&g_cnt[edge_index[EE + i]], 1u);

    float xv = x[i];
    float s = rsqrtf(var[lane] + BN_EPS) * gamma[lane];
    float xb = (xv - mean[lane]) * s + beta[lane];
    g_xbn[i] = xb;

    float y0 = 0.f, y1 = 0.f, y2 = 0.f, y3 = 0.f;
#pragma unroll
    for (int c = 0; c < CC; c += 4) {
        y0 = fmaf(__shfl_sync(0xffffffffu, xb, c    ), sWs[(c    ) * HH + lane], y0);
        y1 = fmaf(__shfl_sync(0xffffffffu, xb, c + 1), sWs[(c + 1) * HH + lane], y1);
        y2 = fmaf(__shfl_sync(0xffffffffu, xb, c + 2), sWs[(c + 2) * HH + lane], y2);
        y3 = fmaf(__shfl_sync(0xffffffffu, xb, c + 3), sWs[(c + 3) * HH + lane], y3);
    }
    g_y[i] = (y0 + y1) + (y2 + y3);
}

// ---------------------------------------------------------------------------
// Kernel 2: fused scan — per-tile exclusive scan, then last block scans tiles
// ---------------------------------------------------------------------------
__global__ void scan_kernel() {
    __shared__ unsigned a[256], b[256];
    int idx = blockIdx.x * 256 + threadIdx.x;
    unsigned v = g_cnt[idx];
    a[threadIdx.x] = v;
    __syncthreads();
    unsigned* s = a; unsigned* d = b;
    for (int o = 1; o < 256; o <<= 1) {
        unsigned t = s[threadIdx.x];
        if (threadIdx.x >= o) t += s[threadIdx.x - o];
        d[threadIdx.x] = t;
        __syncthreads();
        unsigned* tmp = s; s = d; d = tmp;
    }
    unsigned excl = s[threadIdx.x] - v;
    g_rowloc[idx] = excl;
    if (idx < NN) g_cursor[idx] = excl;
    if (threadIdx.x == 255) g_bsum[blockIdx.x] = s[255];

    __shared__ bool isLast;
    __syncthreads();
    if (threadIdx.x == 0) {
        __threadfence();
        isLast = (atomicAdd(&g_scansem, 1u) == (unsigned)(TILES - 1));
    }
    __syncthreads();
    if (isLast) {
        __threadfence();
        unsigned w = (threadIdx.x < TILES) ? g_bsum[threadIdx.x] : 0u;
        a[threadIdx.x] = w;
        __syncthreads();
        s = a; d = b;
        for (int o = 1; o < 256; o <<= 1) {
            unsigned t = s[threadIdx.x];
            if (threadIdx.x >= o) t += s[threadIdx.x - o];
            d[threadIdx.x] = t;
            __syncthreads();
            unsigned* tmp = s; s = d; d = tmp;
        }
        g_tileoff[threadIdx.x] = s[threadIdx.x] - w;
        if (threadIdx.x == 0) g_scansem = 0u;
    }
}

// ---------------------------------------------------------------------------
// Kernel 3: reorder edges into dst buckets (4 edges per thread for atomic MLP)
// ---------------------------------------------------------------------------
#define QE (EE / 4)
__global__ __launch_bounds__(256)
void reorder_kernel(const int* __restrict__ edge_index,
                    const float* __restrict__ edge_weight) {
    int e = blockIdx.x * blockDim.x + threadIdx.x;
    if (e >= QE) return;

    int s0 = edge_index[e];
    int s1 = edge_index[e + QE];
    int s2 = edge_index[e + 2 * QE];
    int s3 = edge_index[e + 3 * QE];
    int d0 = edge_index[EE + e];
    int d1 = edge_index[EE + e + QE];
    int d2 = edge_index[EE + e + 2 * QE];
    int d3 = edge_index[EE + e + 3 * QE];
    float w0 = edge_weight[e];
    float w1 = edge_weight[e + QE];
    float w2 = edge_weight[e + 2 * QE];
    float w3 = edge_weight[e + 3 * QE];

    unsigned p0 = g_tileoff[d0 >> 8] + atomicAdd(&g_cursor[d0], 1u);
    unsigned p1 = g_tileoff[d1 >> 8] + atomicAdd(&g_cursor[d1], 1u);
    unsigned p2 = g_tileoff[d2 >> 8] + atomicAdd(&g_cursor[d2], 1u);
    unsigned p3 = g_tileoff[d3 >> 8] + atomicAdd(&g_cursor[d3], 1u);
    g_edges[p0] = make_uint2((unsigned)s0, __float_as_uint(w0));
    g_edges[p1] = make_uint2((unsigned)s1, __float_as_uint(w1));
    g_edges[p2] = make_uint2((unsigned)s2, __float_as_uint(w2));
    g_edges[p3] = make_uint2((unsigned)s3, __float_as_uint(w3));
}

__device__ __forceinline__ unsigned row_start(int m) {
    return g_tileoff[m >> 8] + g_rowloc[m];
}

// ---------------------------------------------------------------------------
// Interleaved dual-node gather: both rows' loads in flight simultaneously.
// ---------------------------------------------------------------------------
__device__ __forceinline__ void gather_node2(int n0, int n1, int nmax,
                                             const float* sW0,
                                             float& out0, float& out1) {
    const int lane = threadIdx.x & 31;
    unsigned j0 = 0, e0 = 0, j1 = 0, e1 = 0;
    if (n0 < nmax) { j0 = row_start(n0); e0 = row_start(n0 + 1); }
    if (n1 < nmax) { j1 = row_start(n1); e1 = row_start(n1 + 1); }

    float a0 = 0.f, b0 = 0.f, a1 = 0.f, b1 = 0.f;
    while (j0 < e0 || j1 < e1) {
        bool in0 = (j0 + (unsigned)lane < e0);
        bool in1 = (j1 + (unsigned)lane < e1);
        uint2 ed0 = in0 ? g_edges[j0 + lane] : make_uint2(0u, 0u);
        uint2 ed1 = in1 ? g_edges[j1 + lane] : make_uint2(0u, 0u);
        float w0 = in0 ? __uint_as_float(ed0.y) : 0.f;
        float w1 = in1 ? __uint_as_float(ed1.y) : 0.f;

        // rare self-loop(s): k=0 identity term, weight 1 each
        unsigned sl0 = __ballot_sync(0xffffffffu, in0 && ed0.x == (unsigned)n0);
        unsigned sl1 = __ballot_sync(0xffffffffu, in1 && ed1.x == (unsigned)n1);
        if (sl0) {
            float cnt = (float)__popc(sl0);
            float xc = g_xbn[(size_t)n0 * CC + lane];
            float s0 = 0.f;
#pragma unroll
            for (int c = 0; c < CC; c++)
                s0 = fmaf(__shfl_sync(0xffffffffu, xc, c), sW0[c * HH + lane], s0);
            a0 = fmaf(cnt, s0, a0);
        }
        if (sl1) {
            float cnt = (float)__popc(sl1);
            float xc = g_xbn[(size_t)n1 * CC + lane];
            float s1 = 0.f;
#pragma unroll
            for (int c = 0; c < CC; c++)
                s1 = fmaf(__shfl_sync(0xffffffffu, xc, c), sW0[c * HH + lane], s1);
            a1 = fmaf(cnt, s1, a1);
        }

#pragma unroll
        for (int i = 0; i < 32; i += 2) {
            float    wa0 = __shfl_sync(0xffffffffu, w0, i);
            unsigned sa0 = __shfl_sync(0xffffffffu, ed0.x, i);
            float    wb0 = __shfl_sync(0xffffffffu, w0, i + 1);
            unsigned sb0 = __shfl_sync(0xffffffffu, ed0.x, i + 1);
            float    wa1 = __shfl_sync(0xffffffffu, w1, i);
            unsigned sa1 = __shfl_sync(0xffffffffu, ed1.x, i);
            float    wb1 = __shfl_sync(0xffffffffu, w1, i + 1);
            unsigned sb1 = __shfl_sync(0xffffffffu, ed1.x, i + 1);
            a0 = fmaf(wa0, g_y[(size_t)sa0 * HH + lane], a0);
            b0 = fmaf(wb0, g_y[(size_t)sb0 * HH + lane], b0);
            a1 = fmaf(wa1, g_y[(size_t)sa1 * HH + lane], a1);
            b1 = fmaf(wb1, g_y[(size_t)sb1 * HH + lane], b1);
        }
        if (j0 < e0) j0 += 32;
        if (j1 < e1) j1 += 32;
    }
    out0 = fmaxf(a0 + b0, 0.f);
    out1 = fmaxf(a1 + b1, 0.f);
}

// ---------------------------------------------------------------------------
// Kernel 4: fused pipelined CSR gather + fc1 GEMV + head + cleanup
// 128-thread blocks, 4 CTAs/SM -> 4 independent phase domains per SM.
// 8-node tiles; 4 warps gather 2 nodes each (interleaved); gemv 16f x 2 slots.
// ---------------------------------------------------------------------------
__global__ __launch_bounds__(FBLK, 4)
void fused_kernel(const float* __restrict__ W,       // W[0] block for self-loops
                  const float* __restrict__ fc1_w,
                  const float* __restrict__ fc1_b,
                  const float* __restrict__ fc2_w,
                  const float* __restrict__ fc2_b,
                  float* __restrict__ out) {
    __shared__ float sW0[CC * HH];
    __shared__ float sres[2][256];       // 8 nodes x 32 per buffer
    __shared__ float sAcc[FC];
    for (int i = threadIdx.x; i < CC * HH; i += FBLK) sW0[i] = W[i];

    // zero histogram for the NEXT replay (cnt already consumed by scan)
    for (int idx = blockIdx.x * FBLK + threadIdx.x; idx < CNTSZ; idx += FGRID * FBLK)
        g_cnt[idx] = 0u;
    __syncthreads();

    const int tid  = threadIdx.x;
    const int w    = tid >> 5;        // warp 0..3
    const int lane = tid & 31;
    const int nbeg = blockIdx.x * NPB;
    const int nend = min(nbeg + NPB, NN);
    const int nt   = (nend - nbeg + 7) >> 3;   // 8-node tiles

    float acc[16];
#pragma unroll
    for (int k = 0; k < 16; k++) acc[k] = 0.f;

    const float4* W4 = reinterpret_cast<const float4*>(fc1_w);

    // prologue: gather tile 0 (warp w: nodes w and w+4, interleaved)
    {
        float r0, r1;
        gather_node2(nbeg + w, nbeg + 4 + w, nend, sW0, r0, r1);
        sres[0][w * 32 + lane]       = r0;
        sres[0][(w + 4) * 32 + lane] = r1;
    }
    __syncthreads();

    for (int t = 0; t < nt; t++) {
        int cur = t & 1;
        // gather tile t+1 FIRST (loads in flight while gemv streams)
        float rn0 = 0.f, rn1 = 0.f;
        if (t + 1 < nt) {
            int b = nbeg + (t + 1) * 8;
            gather_node2(b + w, b + 4 + w, nend, sW0, rn0, rn1);
        }

        // gemv over tile t: warp w owns f-range [w*16, w*16+16); 2 slot passes
        int t0 = nbeg + t * 8;
        int nv4 = (min(t0 + 8, nend) - t0) * 8;     // valid float4 slots (<=64)
        const float4* R4 = reinterpret_cast<const float4*>(sres[cur]);
#pragma unroll
        for (int p = 0; p < 2; p++) {
            int slot = lane + p * 32;
            if (slot < nv4) {
                float4 rv = R4[slot];
                size_t base = (size_t)t0 * 8 + slot;
#pragma unroll
                for (int k = 0; k < 16; k++) {
                    int f = w * 16 + k;
                    float4 wv = __ldcs(W4 + (size_t)f * NH4 + base);
                    acc[k] = fmaf(rv.x, wv.x, acc[k]);
                    acc[k] = fmaf(rv.y, wv.y, acc[k]);
                    acc[k] = fmaf(rv.z, wv.z, acc[k]);
                    acc[k] = fmaf(rv.w, wv.w, acc[k]);
                }
            }
        }
        sres[1 - cur][w * 32 + lane]       = rn0;
        sres[1 - cur][(w + 4) * 32 + lane] = rn1;
        __syncthreads();
    }

    // reduction: warp w exclusively owns f-range [w*16, w*16+16)
#pragma unroll
    for (int k = 0; k < 16; k++) {
        float v = acc[k];
        v += __shfl_xor_sync(0xffffffffu, v, 16);
        v += __shfl_xor_sync(0xffffffffu, v, 8);
        v += __shfl_xor_sync(0xffffffffu, v, 4);
        v += __shfl_xor_sync(0xffffffffu, v, 2);
        v += __shfl_xor_sync(0xffffffffu, v, 1);
        if (lane == 0) sAcc[w * 16 + k] = v;
    }
    __syncthreads();
    if (tid < FC) atomicAdd(&g_hacc[tid], sAcc[tid]);
    __syncthreads();

    // last block: head + cleanup
    __shared__ bool isLast;
    if (tid == 0) {
        __threadfence();
        isLast = (atomicAdd(&g_sem, 1u) == (unsigned)(FGRID - 1));
    }
    __syncthreads();
    if (isLast) {
        __threadfence();
        __shared__ float hv[FC];
        volatile float* vh = g_hacc;
        if (tid < FC) hv[tid] = fmaxf(vh[tid] + fc1_b[tid], 0.f);
        __syncthreads();
        if (tid < NCLS) {
            float s = fc2_b[tid];
#pragma unroll
            for (int f = 0; f < FC; f++)
                s = fmaf(hv[f], fc2_w[tid * FC + f], s);
            out[tid] = s;
        }
        __syncthreads();
        if (tid < FC) g_hacc[tid] = 0.f;
        if (tid == 0) g_sem = 0u;
    }
}

// ---------------------------------------------------------------------------
// launch
// ---------------------------------------------------------------------------
extern "C" void kernel_launch(void* const* d_in, const int* in_sizes, int n_in,
                              void* d_out, int out_size) {
    const float* x        = (const float*)d_in[0];
    const float* ew       = (const float*)d_in[1];
    const float* W        = (const float*)d_in[2];
    const float* bn_gamma = (const float*)d_in[3];
    const float* bn_beta  = (const float*)d_in[4];
    const float* bn_mean  = (const float*)d_in[5];
    const float* bn_var   = (const float*)d_in[6];
    const float* fc1_w    = (const float*)d_in[7];
    const float* fc1_b    = (const float*)d_in[8];
    const float* fc2_w    = (const float*)d_in[9];
    const float* fc2_b    = (const float*)d_in[10];
    const int*   ei       = (const int*)d_in[11];
    float* out            = (float*)d_out;

    prep_kernel<<<(NN * CC) / 256, 256>>>(x, bn_gamma, bn_beta, bn_mean, bn_var, W, ei);
    scan_kernel<<<TILES, 256>>>();
    reorder_kernel<<<(QE + 255) / 256, 256>>>(ei, ew);
    fused_kernel<<<FGRID, FBLK>>>(W, fc1_w, fc1_b, fc2_w, fc2_b, out);
}